// round 5
// baseline (speedup 1.0000x reference)
#include <cuda_runtime.h>
#include <cuda_bf16.h>

// Problem shapes (fixed for this registry entry)
#define BS  4
#define NPT 8192
#define CH  64
#define MPT 4096
#define KNN 32
#define R2C 0.04f

// FPS decomposition: GCTA CTAs per batch, FPS_T2 threads each.
#define GCTA   8
#define FPS_T2 512
#define PPC    (NPT / GCTA)        // 1024 points per CTA
#define PPT2   (PPC / FPS_T2)      // 2 points per thread

#define BQW 8                      // children (warps) per ball-query block

typedef unsigned long long u64;

// Scratch: transposed feats (bs, n, c). 8 MB.
__device__ float g_feats_t[(size_t)BS * NPT * CH];

// Cross-CTA FPS sync state
__device__ volatile u64      g_results[BS][2][GCTA];  // parity-2 ring of CTA bests
__device__ volatile unsigned g_count[BS];             // monotone arrival counter

// ---------------------------------------------------------------------------
// Faithfully-rounded dx^2+dy^2+dz^2 via error-free transforms (f32 FMA pipe).
// Bit-identical selection behavior established in R3 (rel_err == 0).
// ---------------------------------------------------------------------------
__device__ __forceinline__ float dist2_acc(float dx, float dy, float dz)
{
    const float p1 = __fmul_rn(dx, dx);
    const float e1 = __fmaf_rn(dx, dx, -p1);
    const float p2 = __fmul_rn(dy, dy);
    const float e2 = __fmaf_rn(dy, dy, -p2);
    const float p3 = __fmul_rn(dz, dz);
    const float e3 = __fmaf_rn(dz, dz, -p3);
    const float s1  = __fadd_rn(p1, p2);
    const float b1  = __fsub_rn(s1, p1);
    const float t1  = __fadd_rn(__fsub_rn(p1, __fsub_rn(s1, b1)), __fsub_rn(p2, b1));
    const float s2  = __fadd_rn(s1, p3);
    const float b2  = __fsub_rn(s2, s1);
    const float t2  = __fadd_rn(__fsub_rn(s1, __fsub_rn(s2, b2)), __fsub_rn(p3, b2));
    const float err = __fadd_rn(__fadd_rn(__fadd_rn(e1, e2), e3), __fadd_rn(t1, t2));
    return __fadd_rn(s2, err);
}

// packed argmax key: high 32 = d2 bits (d2 >= 0 so monotonic), low 32 = ~idx
// => u64 max picks max d2, ties pick min idx (jnp.argmax first-occurrence).
__device__ __forceinline__ u64 pack_key(float v, unsigned inv_idx)
{
    return ((u64)__float_as_uint(v) << 32) | inv_idx;
}

__global__ void fps_init_kernel()
{
    if (threadIdx.x < BS) g_count[threadIdx.x] = 0u;
}

// ---------------------------------------------------------------------------
// FPS: GCTA CTAs per batch, global-counter barrier per iteration.
// ---------------------------------------------------------------------------
__global__ void __launch_bounds__(FPS_T2, 1)
fps_kernel(const float* __restrict__ xyz, float* __restrict__ child_xyz)
{
    __shared__ u64 swarp[FPS_T2 / 32];
    __shared__ int scur;

    const int g    = blockIdx.x;            // CTA-within-batch
    const int b    = blockIdx.y;            // batch
    const int tid  = threadIdx.x;
    const int lane = tid & 31;
    const int wid  = tid >> 5;

    const float* __restrict__ X  = xyz + (size_t)b * NPT * 3;
    float* __restrict__       OX = child_xyz + (size_t)b * MPT * 3;

    // this thread's points: idx = g*PPC + k*FPS_T2 + tid
    float px[PPT2], py[PPT2], pz[PPT2], md[PPT2];
    unsigned invi[PPT2];
#pragma unroll
    for (int k = 0; k < PPT2; k++) {
        const int j = g * PPC + k * FPS_T2 + tid;
        px[k] = X[3 * j + 0];
        py[k] = X[3 * j + 1];
        pz[k] = X[3 * j + 2];
        md[k] = 1e10f;
        invi[k] = ~(unsigned)j;
    }

    float cx = X[0], cy = X[1], cz = X[2];

    for (int it = 0; it < MPT; it++) {
        if (g == 0 && tid == 0) {
            OX[3 * it + 0] = cx;
            OX[3 * it + 1] = cy;
            OX[3 * it + 2] = cz;
        }

        u64 best = 0;
#pragma unroll
        for (int k = 0; k < PPT2; k++) {
            const float dx = __fsub_rn(px[k], cx);
            const float dy = __fsub_rn(py[k], cy);
            const float dz = __fsub_rn(pz[k], cz);
            const float d2 = dist2_acc(dx, dy, dz);
            const float nm = fminf(md[k], d2);
            md[k] = nm;
            const u64 key = pack_key(nm, invi[k]);
            if (key > best) best = key;
        }
        // warp argmax (packed compare)
#pragma unroll
        for (int off = 16; off; off >>= 1) {
            const u64 o = __shfl_down_sync(0xffffffffu, best, off);
            if (o > best) best = o;
        }
        if (lane == 0) swarp[wid] = best;
        __syncthreads();

        const int p = it & 1;
        if (wid == 0) {
            if (lane < FPS_T2 / 32) {
                best = swarp[lane];
#pragma unroll
                for (int off = (FPS_T2 / 64); off; off >>= 1) {
                    const u64 o = __shfl_down_sync(0xffffu, best, off, FPS_T2 / 32);
                    if (o > best) best = o;
                }
                if (lane == 0) {
                    g_results[b][p][g] = best;
                    __threadfence();
                    atomicAdd((unsigned*)&g_count[b], 1u);
                }
            }
            if (lane < GCTA) {
                const unsigned target = (unsigned)GCTA * (unsigned)(it + 1);
                while (g_count[b] < target) { }
                __threadfence();
                u64 r = g_results[b][p][lane];
#pragma unroll
                for (int off = GCTA / 2; off; off >>= 1) {
                    const u64 o = __shfl_down_sync((1u << GCTA) - 1u, r, off, GCTA);
                    if (o > r) r = o;
                }
                if (lane == 0) scur = (int)(~(unsigned)r);
            }
        }
        __syncthreads();
        const int cur = scur;
        cx = __ldg(X + 3 * cur + 0);
        cy = __ldg(X + 3 * cur + 1);
        cz = __ldg(X + 3 * cur + 2);
    }
}

// ---------------------------------------------------------------------------
// Transpose feats (bs, C, N) -> g_feats_t (bs, N, C), tiled 32x32.
// ---------------------------------------------------------------------------
__global__ void transpose_kernel(const float* __restrict__ feats)
{
    __shared__ float tile[32][33];
    const int b  = blockIdx.z;
    const int n0 = blockIdx.x * 32;
    const int c0 = blockIdx.y * 32;
    const int tx = threadIdx.x;
    const int ty = threadIdx.y;

    const float* __restrict__ F  = feats + (size_t)b * CH * NPT;
    float* __restrict__       FT = g_feats_t + (size_t)b * NPT * CH;

#pragma unroll
    for (int r = ty; r < 32; r += 8)
        tile[r][tx] = F[(size_t)(c0 + r) * NPT + n0 + tx];
    __syncthreads();
#pragma unroll
    for (int r = ty; r < 32; r += 8)
        FT[(size_t)(n0 + r) * CH + c0 + tx] = tile[tx][r];
}

// ---------------------------------------------------------------------------
// Fused ball query (first-K-within-radius, ascending index) + grouped max.
// ---------------------------------------------------------------------------
__global__ void __launch_bounds__(BQW * 32)
bq_group_kernel(const float* __restrict__ xyz,
                const float* __restrict__ child_xyz,
                float* __restrict__ out_feats)
{
    __shared__ int   nidx[BQW][KNN];
    __shared__ float sfeat[CH][BQW];

    const int b    = blockIdx.y;
    const int j0   = blockIdx.x * BQW;
    const int w    = threadIdx.x >> 5;
    const int lane = threadIdx.x & 31;
    const int j    = j0 + w;

    const float* __restrict__ X = xyz + (size_t)b * NPT * 3;
    const float cx = child_xyz[((size_t)b * MPT + j) * 3 + 0];
    const float cy = child_xyz[((size_t)b * MPT + j) * 3 + 1];
    const float cz = child_xyz[((size_t)b * MPT + j) * 3 + 2];

    int cnt = 0;
    for (int base = 0; base < NPT; base += 32) {
        const int p = base + lane;
        const float dx = __fsub_rn(X[3 * p + 0], cx);
        const float dy = __fsub_rn(X[3 * p + 1], cy);
        const float dz = __fsub_rn(X[3 * p + 2], cz);
        const float d2 = dist2_acc(dx, dy, dz);
        const bool in = (d2 <= R2C);
        const unsigned mask = __ballot_sync(0xffffffffu, in);
        const int pos = cnt + __popc(mask & ((1u << lane) - 1u));
        if (in && pos < KNN) nidx[w][pos] = p;
        cnt += __popc(mask);
        if (cnt >= KNN) break;   // warp-uniform
    }
    if (cnt == 0) { if (lane == 0) nidx[w][0] = 0; cnt = 1; }
    const int kmax = cnt < KNN ? cnt : KNN;
    __syncwarp();

    const float* __restrict__ FT = g_feats_t + (size_t)b * NPT * CH;
    float m0 = -3.4e38f, m1 = -3.4e38f;
    for (int k = 0; k < kmax; k++) {
        const int p = nidx[w][k];
        const float2 v = *(const float2*)(FT + (size_t)p * CH + lane * 2);
        m0 = fmaxf(m0, v.x);
        m1 = fmaxf(m1, v.y);
    }
    sfeat[lane * 2 + 0][w] = m0;
    sfeat[lane * 2 + 1][w] = m1;
    __syncthreads();

    for (int t = threadIdx.x; t < CH * BQW; t += BQW * 32) {
        const int c  = t >> 3;
        const int jj = t & (BQW - 1);
        out_feats[((size_t)b * CH + c) * MPT + j0 + jj] = sfeat[c][jj];
    }
}

// ---------------------------------------------------------------------------
extern "C" void kernel_launch(void* const* d_in, const int* in_sizes, int n_in,
                              void* d_out, int out_size)
{
    const float* xyz   = (const float*)d_in[0];
    const float* feats = (const float*)d_in[1];

    float* out         = (float*)d_out;
    float* child_xyz   = out;                              // (bs, m, 3)
    float* child_feats = out + (size_t)BS * MPT * 3;       // (bs, C, m)

    fps_init_kernel<<<1, 32>>>();
    transpose_kernel<<<dim3(NPT / 32, CH / 32, BS), dim3(32, 8)>>>(feats);
    fps_kernel<<<dim3(GCTA, BS), FPS_T2>>>(xyz, child_xyz);
    bq_group_kernel<<<dim3(MPT / BQW, BS), BQW * 32>>>(xyz, child_xyz, child_feats);
}

// round 7
// speedup vs baseline: 2.7080x; 2.7080x over previous
#include <cuda_runtime.h>
#include <cuda_bf16.h>

// Problem shapes (fixed for this registry entry)
#define BS  4
#define NPT 8192
#define CH  64
#define MPT 4096
#define KNN 32
#define R2C 0.04f

#define FPS_T 1024
#define PPT   (NPT / FPS_T)   // 8 points per thread
#define BQW   8               // children (warps) per ball-query block

// Scratch: transposed feats (bs, n, c). 8 MB.
__device__ float g_feats_t[(size_t)BS * NPT * CH];

// ---------------------------------------------------------------------------
// Faithfully-rounded dx^2+dy^2+dz^2 via error-free transforms (f32 FMA pipe).
// Bit-exact selection behavior established in R3 (rel_err == 0).
// ---------------------------------------------------------------------------
__device__ __forceinline__ float dist2_acc(float dx, float dy, float dz)
{
    const float p1 = __fmul_rn(dx, dx);
    const float e1 = __fmaf_rn(dx, dx, -p1);
    const float p2 = __fmul_rn(dy, dy);
    const float e2 = __fmaf_rn(dy, dy, -p2);
    const float p3 = __fmul_rn(dz, dz);
    const float e3 = __fmaf_rn(dz, dz, -p3);
    const float s1  = __fadd_rn(p1, p2);
    const float b1  = __fsub_rn(s1, p1);
    const float t1  = __fadd_rn(__fsub_rn(p1, __fsub_rn(s1, b1)), __fsub_rn(p2, b1));
    const float s2  = __fadd_rn(s1, p3);
    const float b2  = __fsub_rn(s2, s1);
    const float t2  = __fadd_rn(__fsub_rn(s1, __fsub_rn(s2, b2)), __fsub_rn(p3, b2));
    const float err = __fadd_rn(__fadd_rn(__fadd_rn(e1, e2), e3), __fadd_rn(t1, t2));
    return __fadd_rn(s2, err);
}

// ---------------------------------------------------------------------------
// FPS: one CTA per batch. Certified cheap-filter skips the EFT on the ~94%
// of warp-slots where no lane can possibly lower its min distance.
//
// Invariants (exactness):
//  - md[k] is always the faithful-rounded min distance (only EFT writes it).
//  - skip requires cheap > md*(1+1e-6); since cheap >= faithful*(1-3e-7),
//    skip implies faithful > md, so min(md, faithful) == md. No update lost.
//  - (cmaxv, cmaxi) == argmax_k md[k] with lowest-index tie-break, refreshed
//    whenever any md[k] changes. So each thread's reduction input is exact.
// ---------------------------------------------------------------------------
__global__ void __launch_bounds__(FPS_T, 1)
fps_kernel(const float* __restrict__ xyz, float* __restrict__ child_xyz)
{
    __shared__ float sredv[32];
    __shared__ int   sredi[32];
    __shared__ int   scur;

    const int b    = blockIdx.x;
    const int tid  = threadIdx.x;
    const int lane = tid & 31;
    const int wid  = tid >> 5;

    const float* __restrict__ X  = xyz + (size_t)b * NPT * 3;
    float* __restrict__       OX = child_xyz + (size_t)b * MPT * 3;

    float px[PPT], py[PPT], pz[PPT], md[PPT], thr[PPT];
#pragma unroll
    for (int k = 0; k < PPT; k++) {
        const int j = tid + k * FPS_T;
        px[k] = X[3 * j + 0];
        py[k] = X[3 * j + 1];
        pz[k] = X[3 * j + 2];
        md[k]  = 1e10f;
        thr[k] = 1e10f * 1.000001f;
    }
    // cached per-thread argmax of md[] (all equal -> lowest index = k0)
    float cmaxv = 1e10f;
    int   cmaxi = tid;

    float cx = X[0], cy = X[1], cz = X[2];

    for (int it = 0; it < MPT; it++) {
        if (tid == 0) {
            OX[3 * it + 0] = cx;
            OX[3 * it + 1] = cy;
            OX[3 * it + 2] = cz;
        }

        bool updated = false;
#pragma unroll
        for (int k = 0; k < PPT; k++) {
            const float dx = __fsub_rn(px[k], cx);
            const float dy = __fsub_rn(py[k], cy);
            const float dz = __fsub_rn(pz[k], cz);
            // cheap 3-FMA bound; within ~2.5 ulp of the faithful value
            const float cheap = __fmaf_rn(dz, dz, __fmaf_rn(dy, dy,
                                          __fmul_rn(dx, dx)));
            if (cheap <= thr[k]) {                    // rare (certified filter)
                const float d2 = dist2_acc(dx, dy, dz);
                if (d2 < md[k]) {
                    md[k]  = d2;
                    thr[k] = __fmul_rn(d2, 1.000001f);
                    updated = true;
                }
            }
        }
        if (updated) {                                // rare: refresh cache
            cmaxv = md[0]; cmaxi = tid;
#pragma unroll
            for (int k = 1; k < PPT; k++)
                if (md[k] > cmaxv) { cmaxv = md[k]; cmaxi = tid + k * FPS_T; }
        }

        float bestv = cmaxv;
        int   besti = cmaxi;
        // warp argmax with lowest-index tie-break (jnp.argmax semantics)
#pragma unroll
        for (int off = 16; off; off >>= 1) {
            const float ov = __shfl_down_sync(0xffffffffu, bestv, off);
            const int   oi = __shfl_down_sync(0xffffffffu, besti, off);
            if (ov > bestv || (ov == bestv && oi < besti)) { bestv = ov; besti = oi; }
        }
        if (lane == 0) { sredv[wid] = bestv; sredi[wid] = besti; }
        __syncthreads();
        if (wid == 0) {
            bestv = sredv[lane];
            besti = sredi[lane];
#pragma unroll
            for (int off = 16; off; off >>= 1) {
                const float ov = __shfl_down_sync(0xffffffffu, bestv, off);
                const int   oi = __shfl_down_sync(0xffffffffu, besti, off);
                if (ov > bestv || (ov == bestv && oi < besti)) { bestv = ov; besti = oi; }
            }
            if (lane == 0) scur = besti;
        }
        __syncthreads();
        const int cur = scur;
        // L1-resident broadcast read (all threads, same address)
        cx = __ldg(X + 3 * cur + 0);
        cy = __ldg(X + 3 * cur + 1);
        cz = __ldg(X + 3 * cur + 2);
    }
}

// ---------------------------------------------------------------------------
// Transpose feats (bs, C, N) -> g_feats_t (bs, N, C), tiled 32x32.
// ---------------------------------------------------------------------------
__global__ void transpose_kernel(const float* __restrict__ feats)
{
    __shared__ float tile[32][33];
    const int b  = blockIdx.z;
    const int n0 = blockIdx.x * 32;
    const int c0 = blockIdx.y * 32;
    const int tx = threadIdx.x;
    const int ty = threadIdx.y;

    const float* __restrict__ F  = feats + (size_t)b * CH * NPT;
    float* __restrict__       FT = g_feats_t + (size_t)b * NPT * CH;

#pragma unroll
    for (int r = ty; r < 32; r += 8)
        tile[r][tx] = F[(size_t)(c0 + r) * NPT + n0 + tx];
    __syncthreads();
#pragma unroll
    for (int r = ty; r < 32; r += 8)
        FT[(size_t)(n0 + r) * CH + c0 + tx] = tile[tx][r];
}

// ---------------------------------------------------------------------------
// Fused ball query (first-K-within-radius, ascending index) + grouped max.
// One warp per child; each lane owns 2 channels for the max.
// ---------------------------------------------------------------------------
__global__ void __launch_bounds__(BQW * 32)
bq_group_kernel(const float* __restrict__ xyz,
                const float* __restrict__ child_xyz,
                float* __restrict__ out_feats)
{
    __shared__ int   nidx[BQW][KNN];
    __shared__ float sfeat[CH][BQW];

    const int b    = blockIdx.y;
    const int j0   = blockIdx.x * BQW;
    const int w    = threadIdx.x >> 5;
    const int lane = threadIdx.x & 31;
    const int j    = j0 + w;

    const float* __restrict__ X = xyz + (size_t)b * NPT * 3;
    const float cx = child_xyz[((size_t)b * MPT + j) * 3 + 0];
    const float cy = child_xyz[((size_t)b * MPT + j) * 3 + 1];
    const float cz = child_xyz[((size_t)b * MPT + j) * 3 + 2];

    int cnt = 0;
    for (int base = 0; base < NPT; base += 32) {
        const int p = base + lane;
        const float dx = __fsub_rn(X[3 * p + 0], cx);
        const float dy = __fsub_rn(X[3 * p + 1], cy);
        const float dz = __fsub_rn(X[3 * p + 2], cz);
        const float d2 = dist2_acc(dx, dy, dz);
        const bool in = (d2 <= R2C);
        const unsigned mask = __ballot_sync(0xffffffffu, in);
        const int pos = cnt + __popc(mask & ((1u << lane) - 1u));
        if (in && pos < KNN) nidx[w][pos] = p;
        cnt += __popc(mask);
        if (cnt >= KNN) break;   // warp-uniform
    }
    if (cnt == 0) { if (lane == 0) nidx[w][0] = 0; cnt = 1; }
    const int kmax = cnt < KNN ? cnt : KNN;
    __syncwarp();

    const float* __restrict__ FT = g_feats_t + (size_t)b * NPT * CH;
    float m0 = -3.4e38f, m1 = -3.4e38f;
    for (int k = 0; k < kmax; k++) {
        const int p = nidx[w][k];                 // LDS broadcast
        const float2 v = *(const float2*)(FT + (size_t)p * CH + lane * 2);
        m0 = fmaxf(m0, v.x);
        m1 = fmaxf(m1, v.y);
    }
    sfeat[lane * 2 + 0][w] = m0;
    sfeat[lane * 2 + 1][w] = m1;
    __syncthreads();

    // coalesced staged store of (C x BQW) block
    for (int t = threadIdx.x; t < CH * BQW; t += BQW * 32) {
        const int c  = t >> 3;          // / BQW
        const int jj = t & (BQW - 1);
        out_feats[((size_t)b * CH + c) * MPT + j0 + jj] = sfeat[c][jj];
    }
}

// ---------------------------------------------------------------------------
extern "C" void kernel_launch(void* const* d_in, const int* in_sizes, int n_in,
                              void* d_out, int out_size)
{
    const float* xyz   = (const float*)d_in[0];
    const float* feats = (const float*)d_in[1];

    float* out         = (float*)d_out;
    float* child_xyz   = out;                              // (bs, m, 3)
    float* child_feats = out + (size_t)BS * MPT * 3;       // (bs, C, m)

    transpose_kernel<<<dim3(NPT / 32, CH / 32, BS), dim3(32, 8)>>>(feats);
    fps_kernel<<<BS, FPS_T>>>(xyz, child_xyz);
    bq_group_kernel<<<dim3(MPT / BQW, BS), BQW * 32>>>(xyz, child_xyz, child_feats);
}

// round 8
// speedup vs baseline: 2.9497x; 1.0892x over previous
#include <cuda_runtime.h>
#include <cuda_bf16.h>

// Problem shapes (fixed for this registry entry)
#define BS  4
#define NPT 8192
#define CH  64
#define MPT 4096
#define KNN 32
#define R2C 0.04f

#define FPS_T 1024
#define PPT   (NPT / FPS_T)   // 8 points per thread
#define BQW   8               // children (warps) per ball-query block

typedef unsigned long long u64;

// Scratch: transposed feats (bs, n, c). 8 MB.
__device__ float g_feats_t[(size_t)BS * NPT * CH];

// ---------------------------------------------------------------------------
// Faithfully-rounded dx^2+dy^2+dz^2 via error-free transforms (f32 FMA pipe).
// Bit-exact selection behavior established in R3 (rel_err == 0).
// ---------------------------------------------------------------------------
__device__ __forceinline__ float dist2_acc(float dx, float dy, float dz)
{
    const float p1 = __fmul_rn(dx, dx);
    const float e1 = __fmaf_rn(dx, dx, -p1);
    const float p2 = __fmul_rn(dy, dy);
    const float e2 = __fmaf_rn(dy, dy, -p2);
    const float p3 = __fmul_rn(dz, dz);
    const float e3 = __fmaf_rn(dz, dz, -p3);
    const float s1  = __fadd_rn(p1, p2);
    const float b1  = __fsub_rn(s1, p1);
    const float t1  = __fadd_rn(__fsub_rn(p1, __fsub_rn(s1, b1)), __fsub_rn(p2, b1));
    const float s2  = __fadd_rn(s1, p3);
    const float b2  = __fsub_rn(s2, s1);
    const float t2  = __fadd_rn(__fsub_rn(s1, __fsub_rn(s2, b2)), __fsub_rn(p3, b2));
    const float err = __fadd_rn(__fadd_rn(__fadd_rn(e1, e2), e3), __fadd_rn(t1, t2));
    return __fadd_rn(s2, err);
}

// packed argmax key: high 32 = d2 bits (d2 >= 0 so order-preserving),
// low 32 = ~idx  =>  u64 max == max d2 with lowest-index tie-break
// (jnp.argmax first-occurrence semantics).
__device__ __forceinline__ u64 pack_key(float v, int idx)
{
    return ((u64)__float_as_uint(v) << 32) | (unsigned)(~idx);
}

// ---------------------------------------------------------------------------
// FPS: one CTA per batch.
//  - certified cheap-filter (R7) skips the EFT on ~94% of point-slots
//  - warp-level argmax cache: stage1 shuffle reduce only for "dirty" warps
//  - parity double-buffered per-warp slots -> ONE __syncthreads per iter;
//    stage2 done redundantly by every warp (no broadcast round-trip)
// ---------------------------------------------------------------------------
__global__ void __launch_bounds__(FPS_T, 1)
fps_kernel(const float* __restrict__ xyz, float* __restrict__ child_xyz)
{
    __shared__ u64 sredk[2][32];

    const int b    = blockIdx.x;
    const int tid  = threadIdx.x;
    const int lane = tid & 31;
    const int wid  = tid >> 5;

    const float* __restrict__ X  = xyz + (size_t)b * NPT * 3;
    float* __restrict__       OX = child_xyz + (size_t)b * MPT * 3;

    float px[PPT], py[PPT], pz[PPT], md[PPT], thr[PPT];
#pragma unroll
    for (int k = 0; k < PPT; k++) {
        const int j = tid + k * FPS_T;
        px[k] = X[3 * j + 0];
        py[k] = X[3 * j + 1];
        pz[k] = X[3 * j + 2];
        md[k]  = 1e10f;
        thr[k] = 1e10f * 1.000001f;
    }
    // cached per-thread argmax key over md[] (all equal -> lowest index)
    u64 ckey = pack_key(1e10f, tid);
    // cached per-warp best (valid across iterations; lanes hold copies)
    u64 wkey = 0;

    float cx = X[0], cy = X[1], cz = X[2];

    for (int it = 0; it < MPT; it++) {
        if (tid == 0) {
            OX[3 * it + 0] = cx;
            OX[3 * it + 1] = cy;
            OX[3 * it + 2] = cz;
        }

        bool updated = false;
#pragma unroll
        for (int k = 0; k < PPT; k++) {
            const float dx = __fsub_rn(px[k], cx);
            const float dy = __fsub_rn(py[k], cy);
            const float dz = __fsub_rn(pz[k], cz);
            // cheap 3-FMA bound; within ~2.5 ulp of the faithful value
            const float cheap = __fmaf_rn(dz, dz, __fmaf_rn(dy, dy,
                                          __fmul_rn(dx, dx)));
            if (cheap <= thr[k]) {                    // rare (certified filter)
                const float d2 = dist2_acc(dx, dy, dz);
                if (d2 < md[k]) {
                    md[k]  = d2;
                    thr[k] = __fmul_rn(d2, 1.000001f);
                    updated = true;
                }
            }
        }

        // stage1: only dirty warps re-reduce (md is monotone non-increasing,
        // so a warp's best can change only if one of its lanes updated)
        const unsigned dirty = __ballot_sync(0xffffffffu, updated);
        if (dirty) {
            if (updated) {                            // refresh thread cache
                ckey = pack_key(md[0], tid);
#pragma unroll
                for (int k = 1; k < PPT; k++) {
                    const u64 kk = pack_key(md[k], tid + k * FPS_T);
                    if (kk > ckey) ckey = kk;
                }
            }
            u64 r = ckey;
#pragma unroll
            for (int off = 16; off; off >>= 1) {
                const u64 o = __shfl_xor_sync(0xffffffffu, r, off);
                if (o > r) r = o;
            }
            wkey = r;                                 // all lanes hold it
        }
        if (lane == 0) sredk[it & 1][wid] = wkey;     // always repost (parity)
        __syncthreads();

        // stage2: every warp redundantly reduces the 32 per-warp slots
        u64 best = sredk[it & 1][lane];
#pragma unroll
        for (int off = 16; off; off >>= 1) {
            const u64 o = __shfl_xor_sync(0xffffffffu, best, off);
            if (o > best) best = o;
        }
        const int cur = (int)(~(unsigned)best);

        // L1-resident broadcast read (all threads, same address)
        cx = __ldg(X + 3 * cur + 0);
        cy = __ldg(X + 3 * cur + 1);
        cz = __ldg(X + 3 * cur + 2);
    }
}

// ---------------------------------------------------------------------------
// Transpose feats (bs, C, N) -> g_feats_t (bs, N, C), tiled 32x32.
// ---------------------------------------------------------------------------
__global__ void transpose_kernel(const float* __restrict__ feats)
{
    __shared__ float tile[32][33];
    const int b  = blockIdx.z;
    const int n0 = blockIdx.x * 32;
    const int c0 = blockIdx.y * 32;
    const int tx = threadIdx.x;
    const int ty = threadIdx.y;

    const float* __restrict__ F  = feats + (size_t)b * CH * NPT;
    float* __restrict__       FT = g_feats_t + (size_t)b * NPT * CH;

#pragma unroll
    for (int r = ty; r < 32; r += 8)
        tile[r][tx] = F[(size_t)(c0 + r) * NPT + n0 + tx];
    __syncthreads();
#pragma unroll
    for (int r = ty; r < 32; r += 8)
        FT[(size_t)(n0 + r) * CH + c0 + tx] = tile[tx][r];
}

// ---------------------------------------------------------------------------
// Fused ball query (first-K-within-radius, ascending index) + grouped max.
// One warp per child; each lane owns 2 channels for the max.
// ---------------------------------------------------------------------------
__global__ void __launch_bounds__(BQW * 32)
bq_group_kernel(const float* __restrict__ xyz,
                const float* __restrict__ child_xyz,
                float* __restrict__ out_feats)
{
    __shared__ int   nidx[BQW][KNN];
    __shared__ float sfeat[CH][BQW];

    const int b    = blockIdx.y;
    const int j0   = blockIdx.x * BQW;
    const int w    = threadIdx.x >> 5;
    const int lane = threadIdx.x & 31;
    const int j    = j0 + w;

    const float* __restrict__ X = xyz + (size_t)b * NPT * 3;
    const float cx = child_xyz[((size_t)b * MPT + j) * 3 + 0];
    const float cy = child_xyz[((size_t)b * MPT + j) * 3 + 1];
    const float cz = child_xyz[((size_t)b * MPT + j) * 3 + 2];

    int cnt = 0;
    for (int base = 0; base < NPT; base += 32) {
        const int p = base + lane;
        const float dx = __fsub_rn(X[3 * p + 0], cx);
        const float dy = __fsub_rn(X[3 * p + 1], cy);
        const float dz = __fsub_rn(X[3 * p + 2], cz);
        const float d2 = dist2_acc(dx, dy, dz);
        const bool in = (d2 <= R2C);
        const unsigned mask = __ballot_sync(0xffffffffu, in);
        const int pos = cnt + __popc(mask & ((1u << lane) - 1u));
        if (in && pos < KNN) nidx[w][pos] = p;
        cnt += __popc(mask);
        if (cnt >= KNN) break;   // warp-uniform
    }
    if (cnt == 0) { if (lane == 0) nidx[w][0] = 0; cnt = 1; }
    const int kmax = cnt < KNN ? cnt : KNN;
    __syncwarp();

    const float* __restrict__ FT = g_feats_t + (size_t)b * NPT * CH;
    float m0 = -3.4e38f, m1 = -3.4e38f;
    for (int k = 0; k < kmax; k++) {
        const int p = nidx[w][k];                 // LDS broadcast
        const float2 v = *(const float2*)(FT + (size_t)p * CH + lane * 2);
        m0 = fmaxf(m0, v.x);
        m1 = fmaxf(m1, v.y);
    }
    sfeat[lane * 2 + 0][w] = m0;
    sfeat[lane * 2 + 1][w] = m1;
    __syncthreads();

    // coalesced staged store of (C x BQW) block
    for (int t = threadIdx.x; t < CH * BQW; t += BQW * 32) {
        const int c  = t >> 3;          // / BQW
        const int jj = t & (BQW - 1);
        out_feats[((size_t)b * CH + c) * MPT + j0 + jj] = sfeat[c][jj];
    }
}

// ---------------------------------------------------------------------------
extern "C" void kernel_launch(void* const* d_in, const int* in_sizes, int n_in,
                              void* d_out, int out_size)
{
    const float* xyz   = (const float*)d_in[0];
    const float* feats = (const float*)d_in[1];

    float* out         = (float*)d_out;
    float* child_xyz   = out;                              // (bs, m, 3)
    float* child_feats = out + (size_t)BS * MPT * 3;       // (bs, C, m)

    transpose_kernel<<<dim3(NPT / 32, CH / 32, BS), dim3(32, 8)>>>(feats);
    fps_kernel<<<BS, FPS_T>>>(xyz, child_xyz);
    bq_group_kernel<<<dim3(MPT / BQW, BS), BQW * 32>>>(xyz, child_xyz, child_feats);
}

// round 9
// speedup vs baseline: 3.0611x; 1.0378x over previous
#include <cuda_runtime.h>
#include <cuda_bf16.h>

// Problem shapes (fixed for this registry entry)
#define BS  4
#define NPT 8192
#define CH  64
#define MPT 4096
#define KNN 32
#define R2C  0.04f
#define R2LO 0.03999996f   // R2*(1-1e-6): cheap <= R2LO  => faithful <= R2
#define R2HI 0.04000004f   // R2*(1+1e-6): cheap >  R2HI  => faithful >  R2

#define FPS_T 1024
#define PPT   (NPT / FPS_T)   // 8 points per thread
#define BQW   8               // children (warps) per ball-query block
#define FULLM 0xffffffffu

typedef unsigned long long u64;

// Scratch: transposed feats (bs, n, c). 8 MB.
__device__ float g_feats_t[(size_t)BS * NPT * CH];

// ---------------------------------------------------------------------------
// Faithfully-rounded dx^2+dy^2+dz^2 via error-free transforms (f32 FMA pipe).
// Bit-exact selection behavior established in R3 (rel_err == 0).
// ---------------------------------------------------------------------------
__device__ __forceinline__ float dist2_acc(float dx, float dy, float dz)
{
    const float p1 = __fmul_rn(dx, dx);
    const float e1 = __fmaf_rn(dx, dx, -p1);
    const float p2 = __fmul_rn(dy, dy);
    const float e2 = __fmaf_rn(dy, dy, -p2);
    const float p3 = __fmul_rn(dz, dz);
    const float e3 = __fmaf_rn(dz, dz, -p3);
    const float s1  = __fadd_rn(p1, p2);
    const float b1  = __fsub_rn(s1, p1);
    const float t1  = __fadd_rn(__fsub_rn(p1, __fsub_rn(s1, b1)), __fsub_rn(p2, b1));
    const float s2  = __fadd_rn(s1, p3);
    const float b2  = __fsub_rn(s2, s1);
    const float t2  = __fadd_rn(__fsub_rn(s1, __fsub_rn(s2, b2)), __fsub_rn(p3, b2));
    const float err = __fadd_rn(__fadd_rn(__fadd_rn(e1, e2), e3), __fadd_rn(t1, t2));
    return __fadd_rn(s2, err);
}

// packed argmax key: high 32 = d2 bits (d2 >= 0 so order-preserving),
// low 32 = ~idx  =>  max key == max d2 with lowest-index tie-break.
__device__ __forceinline__ u64 pack_key(float v, int idx)
{
    return ((u64)__float_as_uint(v) << 32) | (unsigned)(~idx);
}

// ---------------------------------------------------------------------------
// FPS: one CTA per batch.
//  - certified cheap-filter (R7) skips the EFT on ~94% of point-slots
//  - dirty-warp-only stage1; redux.sync argmax (value then ~idx tie-break)
//  - coords travel in the smem slots: no __ldg chain, one barrier per iter
// ---------------------------------------------------------------------------
__global__ void __launch_bounds__(FPS_T, 1)
fps_kernel(const float* __restrict__ xyz, float* __restrict__ child_xyz)
{
    __shared__ u64   skey[2][32];
    __shared__ float sx[2][32], sy[2][32], sz[2][32];

    const int b    = blockIdx.x;
    const int tid  = threadIdx.x;
    const int lane = tid & 31;
    const int wid  = tid >> 5;

    const float* __restrict__ X  = xyz + (size_t)b * NPT * 3;
    float* __restrict__       OX = child_xyz + (size_t)b * MPT * 3;

    float px[PPT], py[PPT], pz[PPT], md[PPT];
#pragma unroll
    for (int k = 0; k < PPT; k++) {
        const int j = tid + k * FPS_T;
        px[k] = X[3 * j + 0];
        py[k] = X[3 * j + 1];
        pz[k] = X[3 * j + 2];
        md[k] = 1e10f;
    }
    // thread-best cache: key + that point's coords (all md equal -> k=0)
    u64   ckey = pack_key(1e10f, tid);
    float ax = px[0], ay = py[0], az = pz[0];
    // warp-best cache (held by all lanes; lane0 reposts it each iter)
    u64   wkey = 0;
    float wx = 0.f, wy = 0.f, wz = 0.f;

    float cx = X[0], cy = X[1], cz = X[2];

    for (int it = 0; it < MPT; it++) {
        if (tid == 0) {
            OX[3 * it + 0] = cx;
            OX[3 * it + 1] = cy;
            OX[3 * it + 2] = cz;
        }

        bool updated = false;
#pragma unroll
        for (int k = 0; k < PPT; k++) {
            const float dx = __fsub_rn(px[k], cx);
            const float dy = __fsub_rn(py[k], cy);
            const float dz = __fsub_rn(pz[k], cz);
            // cheap 3-FMA bound; within ~2.5 ulp of the faithful value
            const float cheap = __fmaf_rn(dz, dz, __fmaf_rn(dy, dy,
                                          __fmul_rn(dx, dx)));
            if (cheap <= __fmul_rn(md[k], 1.000001f)) {   // certified filter
                const float d2 = dist2_acc(dx, dy, dz);
                if (d2 < md[k]) { md[k] = d2; updated = true; }
            }
        }

        // stage1: only dirty warps re-reduce (md monotone non-increasing)
        const unsigned dirty = __ballot_sync(FULLM, updated);
        if (dirty) {
            if (updated) {                      // refresh thread cache
                float bv = md[0]; int bi = tid;
                float tx = px[0], ty = py[0], tz = pz[0];
#pragma unroll
                for (int k = 1; k < PPT; k++)
                    if (md[k] > bv) {
                        bv = md[k]; bi = tid + k * FPS_T;
                        tx = px[k]; ty = py[k]; tz = pz[k];
                    }
                ckey = pack_key(bv, bi);
                ax = tx; ay = ty; az = tz;
            }
            const unsigned hi = (unsigned)(ckey >> 32);
            const unsigned lo = (unsigned)ckey;
            const unsigned mh = __reduce_max_sync(FULLM, hi);
            const unsigned ml = __reduce_max_sync(FULLM, (hi == mh) ? lo : 0u);
            wkey = ((u64)mh << 32) | ml;
            const bool win = (hi == mh) && (lo == ml);   // unique lane
            const int  wl  = __ffs(__ballot_sync(FULLM, win)) - 1;
            wx = __shfl_sync(FULLM, ax, wl);
            wy = __shfl_sync(FULLM, ay, wl);
            wz = __shfl_sync(FULLM, az, wl);
        }
        const int p = it & 1;
        if (lane == 0) {
            skey[p][wid] = wkey;
            sx[p][wid] = wx; sy[p][wid] = wy; sz[p][wid] = wz;
        }
        __syncthreads();

        // stage2: every warp reduces the 32 per-warp slots via redux
        const u64 k2       = skey[p][lane];
        const unsigned hi2 = (unsigned)(k2 >> 32);
        const unsigned lo2 = (unsigned)k2;
        const unsigned mh2 = __reduce_max_sync(FULLM, hi2);
        const unsigned ml2 = __reduce_max_sync(FULLM, (hi2 == mh2) ? lo2 : 0u);
        const bool match   = (hi2 == mh2) && (lo2 == ml2);
        const int  s       = __ffs(__ballot_sync(FULLM, match)) - 1;
        cx = sx[p][s]; cy = sy[p][s]; cz = sz[p][s];      // broadcast LDS
    }
}

// ---------------------------------------------------------------------------
// Transpose feats (bs, C, N) -> g_feats_t (bs, N, C), tiled 32x32.
// ---------------------------------------------------------------------------
__global__ void transpose_kernel(const float* __restrict__ feats)
{
    __shared__ float tile[32][33];
    const int b  = blockIdx.z;
    const int n0 = blockIdx.x * 32;
    const int c0 = blockIdx.y * 32;
    const int tx = threadIdx.x;
    const int ty = threadIdx.y;

    const float* __restrict__ F  = feats + (size_t)b * CH * NPT;
    float* __restrict__       FT = g_feats_t + (size_t)b * NPT * CH;

#pragma unroll
    for (int r = ty; r < 32; r += 8)
        tile[r][tx] = F[(size_t)(c0 + r) * NPT + n0 + tx];
    __syncthreads();
#pragma unroll
    for (int r = ty; r < 32; r += 8)
        FT[(size_t)(n0 + r) * CH + c0 + tx] = tile[tx][r];
}

// ---------------------------------------------------------------------------
// Fused ball query (first-K-within-radius, ascending index) + grouped max.
// Certified cheap filter: EFT only in the 1e-6-wide boundary band.
// ---------------------------------------------------------------------------
__global__ void __launch_bounds__(BQW * 32)
bq_group_kernel(const float* __restrict__ xyz,
                const float* __restrict__ child_xyz,
                float* __restrict__ out_feats)
{
    __shared__ int   nidx[BQW][KNN];
    __shared__ float sfeat[CH][BQW];

    const int b    = blockIdx.y;
    const int j0   = blockIdx.x * BQW;
    const int w    = threadIdx.x >> 5;
    const int lane = threadIdx.x & 31;
    const int j    = j0 + w;

    const float* __restrict__ X = xyz + (size_t)b * NPT * 3;
    const float cx = child_xyz[((size_t)b * MPT + j) * 3 + 0];
    const float cy = child_xyz[((size_t)b * MPT + j) * 3 + 1];
    const float cz = child_xyz[((size_t)b * MPT + j) * 3 + 2];

    int cnt = 0;
    for (int base = 0; base < NPT; base += 32) {
        const int p = base + lane;
        const float dx = __fsub_rn(X[3 * p + 0], cx);
        const float dy = __fsub_rn(X[3 * p + 1], cy);
        const float dz = __fsub_rn(X[3 * p + 2], cz);
        const float cheap = __fmaf_rn(dz, dz, __fmaf_rn(dy, dy,
                                      __fmul_rn(dx, dx)));
        bool in = (cheap <= R2LO);                         // certified in
        if (cheap > R2LO && cheap <= R2HI)                 // boundary band
            in = (dist2_acc(dx, dy, dz) <= R2C);
        const unsigned mask = __ballot_sync(FULLM, in);
        const int pos = cnt + __popc(mask & ((1u << lane) - 1u));
        if (in && pos < KNN) nidx[w][pos] = p;
        cnt += __popc(mask);
        if (cnt >= KNN) break;   // warp-uniform
    }
    if (cnt == 0) { if (lane == 0) nidx[w][0] = 0; cnt = 1; }
    const int kmax = cnt < KNN ? cnt : KNN;
    __syncwarp();

    const float* __restrict__ FT = g_feats_t + (size_t)b * NPT * CH;
    float m0 = -3.4e38f, m1 = -3.4e38f;
    for (int k = 0; k < kmax; k++) {
        const int p = nidx[w][k];                 // LDS broadcast
        const float2 v = *(const float2*)(FT + (size_t)p * CH + lane * 2);
        m0 = fmaxf(m0, v.x);
        m1 = fmaxf(m1, v.y);
    }
    sfeat[lane * 2 + 0][w] = m0;
    sfeat[lane * 2 + 1][w] = m1;
    __syncthreads();

    // coalesced staged store of (C x BQW) block
    for (int t = threadIdx.x; t < CH * BQW; t += BQW * 32) {
        const int c  = t >> 3;          // / BQW
        const int jj = t & (BQW - 1);
        out_feats[((size_t)b * CH + c) * MPT + j0 + jj] = sfeat[c][jj];
    }
}

// ---------------------------------------------------------------------------
extern "C" void kernel_launch(void* const* d_in, const int* in_sizes, int n_in,
                              void* d_out, int out_size)
{
    const float* xyz   = (const float*)d_in[0];
    const float* feats = (const float*)d_in[1];

    float* out         = (float*)d_out;
    float* child_xyz   = out;                              // (bs, m, 3)
    float* child_feats = out + (size_t)BS * MPT * 3;       // (bs, C, m)

    transpose_kernel<<<dim3(NPT / 32, CH / 32, BS), dim3(32, 8)>>>(feats);
    fps_kernel<<<BS, FPS_T>>>(xyz, child_xyz);
    bq_group_kernel<<<dim3(MPT / BQW, BS), BQW * 32>>>(xyz, child_xyz, child_feats);
}